// round 6
// baseline (speedup 1.0000x reference)
#include <cuda_runtime.h>
#include <math.h>

// Problem constants: N=16384, H=32, G=8, D=128, FF=2, R=4, GROUPS=4, NBAND=32
#define NTOK 16384
#define QK_TPB 4
#define W_TPB 8
#define NQK (NTOK / QK_TPB)   // 4096 qk blocks
#define NW  (NTOK / W_TPB)    // 2048 w blocks

// Output layout in d_out (floats): index_q [N][4][128], index_k [N][128], weights [N][4]
#define OUT_Q_OFF ((size_t)0)
#define OUT_K_OFF ((size_t)NTOK * 512)
#define OUT_W_OFF ((size_t)NTOK * 512 + (size_t)NTOK * 128)

// smem used only by the W path: VS[8][1024] + RED[8][8][4] = 8448 floats
#define SMEM_FLOATS 8448

// QK path (register-only fold, partial-sum exchange):
//   lane = band (bm = lane&15, fb = lane>>4).
//   float4 at (h = gh*4+gr, d = hf*64 + 4*bm):
//     x->(band=bm,feat=gh)  y->(band=16+bm,feat=gh)
//     z->(band=bm,feat=8+gh) w->(band=16+bm,feat=8+gh)
//   Lane loads gh = fb*4+j (j=0..3). It computes the partial dot for its OWN
//   band over those 8 feats AND the partial for the partner band (lane^16)
//   over the same feats; one shfl_xor(16) of the partner partials completes
//   both bands. Coefficients: cO = proj[lane][F_fb], cX = proj[lane^16][F_fb].

__global__ __launch_bounds__(256, 3) void fused_kernel(
    const float* __restrict__ q,
    const float* __restrict__ k,
    const float* __restrict__ v,
    const float* __restrict__ proj,   // [32][16][2]
    const float* __restrict__ vt,     // [32][128][4]
    float* __restrict__ out)
{
    extern __shared__ float smem[];
    const int tid = threadIdx.x;

    if (blockIdx.x < NQK) {
        // ================= QK path (no smem, no barriers) =================
        const int lane = tid & 31;
        const int w    = tid >> 5;        // warp 0..7
        const int bm   = lane & 15;
        const int fb   = lane >> 4;       // band == lane
        const int gr   = w & 3;           // q group for this warp
        const int hf   = w >> 2;          // q half for this warp
        const int n0   = blockIdx.x * QK_TPB;

        // ---- coefficients: own band row + partner band row, feat block F_fb ----
        float4 cO[4], cX[4];
        {
            const float4* po = (const float4*)(proj + lane * 32);
            const float4* px = (const float4*)(proj + (lane ^ 16) * 32);
            cO[0] = __ldg(&po[fb * 2]);     cO[1] = __ldg(&po[fb * 2 + 1]);
            cO[2] = __ldg(&po[4 + fb * 2]); cO[3] = __ldg(&po[4 + fb * 2 + 1]);
            cX[0] = __ldg(&px[fb * 2]);     cX[1] = __ldg(&px[fb * 2 + 1]);
            cX[2] = __ldg(&px[4 + fb * 2]); cX[3] = __ldg(&px[4 + fb * 2 + 1]);
        }

        // ---- K job: warp w -> (tok = w>>1, hh = w&1) ----
        {
            const int n  = n0 + (w >> 1);
            const int hh = w & 1;
            const float* kb = k + (size_t)n * 1024 + fb * 512 + hh * 64 + 4 * bm;
            float4 L[4];
            #pragma unroll
            for (int j = 0; j < 4; j++)
                L[j] = __ldg((const float4*)(kb + j * 128));
            float aO0 = 0.f, aO1 = 0.f, aX0 = 0.f, aX1 = 0.f;
            #pragma unroll
            for (int j = 0; j < 4; j++) {
                const float olo = fb ? L[j].y : L[j].x;
                const float ohi = fb ? L[j].w : L[j].z;
                const float xlo = fb ? L[j].x : L[j].y;
                const float xhi = fb ? L[j].z : L[j].w;
                const float4 fol = cO[j >> 1], foh = cO[2 + (j >> 1)];
                const float4 fxl = cX[j >> 1], fxh = cX[2 + (j >> 1)];
                if (j & 1) {
                    aO0 = fmaf(olo, fol.z, fmaf(ohi, foh.z, aO0));
                    aO1 = fmaf(olo, fol.w, fmaf(ohi, foh.w, aO1));
                    aX0 = fmaf(xlo, fxl.z, fmaf(xhi, fxh.z, aX0));
                    aX1 = fmaf(xlo, fxl.w, fmaf(xhi, fxh.w, aX1));
                } else {
                    aO0 = fmaf(olo, fol.x, fmaf(ohi, foh.x, aO0));
                    aO1 = fmaf(olo, fol.y, fmaf(ohi, foh.y, aO1));
                    aX0 = fmaf(xlo, fxl.x, fmaf(xhi, fxh.x, aX0));
                    aX1 = fmaf(xlo, fxl.y, fmaf(xhi, fxh.y, aX1));
                }
            }
            const float a0 = aO0 + __shfl_xor_sync(0xffffffffu, aX0, 16);
            const float a1 = aO1 + __shfl_xor_sync(0xffffffffu, aX1, 16);
            float2* o = (float2*)(out + OUT_K_OFF + (size_t)n * 128 +
                                  hh * 64 + lane * 2);
            *o = make_float2(a0, a1);
        }

        // ---- Q: 4 tokens, 2-deep software pipeline (8 LDG.128 in flight) ----
        const float* qb = q + (size_t)n0 * 4096 + (size_t)fb * 2048 +
                          gr * 128 + hf * 64 + 4 * bm;
        float4 A[4], B[4];
        #pragma unroll
        for (int j = 0; j < 4; j++) A[j] = __ldg((const float4*)(qb + j * 512));
        #pragma unroll
        for (int j = 0; j < 4; j++) B[j] = __ldg((const float4*)(qb + 4096 + j * 512));

        #pragma unroll
        for (int t = 0; t < QK_TPB; t++) {
            float4* Lc = (t & 1) ? B : A;
            float aO0 = 0.f, aO1 = 0.f, aX0 = 0.f, aX1 = 0.f;
            #pragma unroll
            for (int j = 0; j < 4; j++) {
                const float olo = fb ? Lc[j].y : Lc[j].x;
                const float ohi = fb ? Lc[j].w : Lc[j].z;
                const float xlo = fb ? Lc[j].x : Lc[j].y;
                const float xhi = fb ? Lc[j].z : Lc[j].w;
                const float4 fol = cO[j >> 1], foh = cO[2 + (j >> 1)];
                const float4 fxl = cX[j >> 1], fxh = cX[2 + (j >> 1)];
                if (j & 1) {
                    aO0 = fmaf(olo, fol.z, fmaf(ohi, foh.z, aO0));
                    aO1 = fmaf(olo, fol.w, fmaf(ohi, foh.w, aO1));
                    aX0 = fmaf(xlo, fxl.z, fmaf(xhi, fxh.z, aX0));
                    aX1 = fmaf(xlo, fxl.w, fmaf(xhi, fxh.w, aX1));
                } else {
                    aO0 = fmaf(olo, fol.x, fmaf(ohi, foh.x, aO0));
                    aO1 = fmaf(olo, fol.y, fmaf(ohi, foh.y, aO1));
                    aX0 = fmaf(xlo, fxl.x, fmaf(xhi, fxh.x, aX0));
                    aX1 = fmaf(xlo, fxl.y, fmaf(xhi, fxh.y, aX1));
                }
            }
            // prefetch token t+2 into the buffer just consumed
            if (t + 2 < QK_TPB) {
                const float* qn = qb + (size_t)(t + 2) * 4096;
                #pragma unroll
                for (int j = 0; j < 4; j++)
                    Lc[j] = __ldg((const float4*)(qn + j * 512));
            }
            const float a0 = aO0 + __shfl_xor_sync(0xffffffffu, aX0, 16);
            const float a1 = aO1 + __shfl_xor_sync(0xffffffffu, aX1, 16);
            float2* o = (float2*)(out + OUT_Q_OFF + (size_t)(n0 + t) * 512 +
                                  gr * 128 + hf * 64 + lane * 2);
            *o = make_float2(a0, a1);
        }
    } else {
        // ================= W path =================
        float* VS  = smem;            // [W_TPB][1024]
        float* RED = smem + 8192;     // [tok][g][t]

        const int dseg = tid & 7;
        const int t    = (tid >> 3) & 3;
        const int g    = tid >> 5;
        const int h    = g * 4 + t;

        // vt slice in registers
        float4 wt[16];
        {
            const float4* vt4 = (const float4*)vt;
            #pragma unroll
            for (int i = 0; i < 16; i++)
                wt[i] = __ldg(&vt4[h * 128 + dseg + 8 * i]);
        }

        const int n0 = (blockIdx.x - NQK) * W_TPB;

        // stage W_TPB v rows (coalesced)
        {
            const float4* v4 = (const float4*)v + (size_t)n0 * 256;
            float4* vs4 = (float4*)VS;
            #pragma unroll
            for (int j = 0; j < W_TPB; j++)
                vs4[tid + 256 * j] = v4[tid + 256 * j];
        }
        __syncthreads();

        #pragma unroll
        for (int tok = 0; tok < W_TPB; tok++) {
            float4 a = make_float4(0.f, 0.f, 0.f, 0.f);
            float4 b = make_float4(0.f, 0.f, 0.f, 0.f);
            const float* vrow = VS + tok * 1024 + g * 128 + dseg;
            #pragma unroll
            for (int i = 0; i < 16; i += 2) {
                const float f0 = vrow[8 * i];
                const float f1 = vrow[8 * (i + 1)];
                a.x = fmaf(f0, wt[i].x, a.x);     b.x = fmaf(f1, wt[i+1].x, b.x);
                a.y = fmaf(f0, wt[i].y, a.y);     b.y = fmaf(f1, wt[i+1].y, b.y);
                a.z = fmaf(f0, wt[i].z, a.z);     b.z = fmaf(f1, wt[i+1].z, b.z);
                a.w = fmaf(f0, wt[i].w, a.w);     b.w = fmaf(f1, wt[i+1].w, b.w);
            }
            a.x += b.x; a.y += b.y; a.z += b.z; a.w += b.w;
            #pragma unroll
            for (int m = 1; m <= 4; m <<= 1) {
                a.x += __shfl_xor_sync(0xffffffffu, a.x, m);
                a.y += __shfl_xor_sync(0xffffffffu, a.y, m);
                a.z += __shfl_xor_sync(0xffffffffu, a.z, m);
                a.w += __shfl_xor_sync(0xffffffffu, a.w, m);
            }
            if (dseg == 0)
                RED[(tok * 8 + g) * 4 + t] =
                    a.x * a.x + a.y * a.y + a.z * a.z + a.w * a.w;
        }
        __syncthreads();

        if (tid < W_TPB * 4) {
            const int tok = tid >> 2;
            const int tt  = tid & 3;
            float s = 0.f;
            #pragma unroll
            for (int gg = 0; gg < 8; gg++) s += RED[(tok * 8 + gg) * 4 + tt];
            out[OUT_W_OFF + (size_t)(n0 + tok) * 4 + tt] = sqrtf(s);
        }
    }
}

extern "C" void kernel_launch(void* const* d_in, const int* in_sizes, int n_in,
                              void* d_out, int out_size)
{
    const float* q    = (const float*)d_in[0];   // [16384][32][128]
    const float* k    = (const float*)d_in[1];   // [16384][8][128]
    const float* v    = (const float*)d_in[2];   // [16384][8][128]
    const float* proj = (const float*)d_in[3];   // [32][16][2]
    const float* vt   = (const float*)d_in[4];   // [32][128][4]
    float* out = (float*)d_out;

    fused_kernel<<<NQK + NW, 256, SMEM_FLOATS * sizeof(float)>>>(
        q, k, v, proj, vt, out);
}

// round 7
// speedup vs baseline: 1.5333x; 1.5333x over previous
#include <cuda_runtime.h>
#include <math.h>

// Problem constants: N=16384, H=32, G=8, D=128, FF=2, R=4, GROUPS=4, NBAND=32
#define NTOK 16384
#define QK_TPB 8
#define W_TPB 8
#define NQK (NTOK / QK_TPB)   // 2048 qk blocks
#define NW  (NTOK / W_TPB)    // 2048 w blocks

// Output layout in d_out (floats): index_q [N][4][128], index_k [N][128], weights [N][4]
#define OUT_Q_OFF ((size_t)0)
#define OUT_K_OFF ((size_t)NTOK * 512)
#define OUT_W_OFF ((size_t)NTOK * 512 + (size_t)NTOK * 128)

// smem: w path needs 8448 floats; qk path needs 32*33=1056 for padded proj.
#define SMEM_FLOATS 8448

// QK path (register-only fold, partial-sum exchange):
//   lane = band (bm = lane&15, fb = lane>>4).
//   float4 at (h = gh*4+gr, d = hf*64 + 4*bm):
//     x->(band=bm,feat=gh)  y->(band=16+bm,feat=gh)
//     z->(band=bm,feat=8+gh) w->(band=16+bm,feat=8+gh)
//   Lane loads gh = fb*4+j (j=0..3); computes own-band partial AND partner-band
//   (lane^16) partial over those 8 feats; one shfl_xor(16) of partner partials
//   completes both bands. Coefficients staged via padded smem [32][33].

__global__ __launch_bounds__(256, 3) void fused_kernel(
    const float* __restrict__ q,
    const float* __restrict__ k,
    const float* __restrict__ v,
    const float* __restrict__ proj,   // [32][16][2]
    const float* __restrict__ vt,     // [32][128][4]
    float* __restrict__ out)
{
    extern __shared__ float smem[];
    const int tid = threadIdx.x;

    if (blockIdx.x < NQK) {
        // ================= QK path =================
        float* SP = smem;                 // padded proj [32][33]
        const int lane = tid & 31;
        const int w    = tid >> 5;        // warp 0..7
        const int bm   = lane & 15;
        const int fb   = lane >> 4;       // band == lane
        const int gr   = w & 3;           // q group for this warp
        const int hf   = w >> 2;          // q half for this warp
        const int n0   = blockIdx.x * QK_TPB;

        // stage proj into padded smem (coalesced LDG, conflict-free STS)
        {
            const float4 p = __ldg(&((const float4*)proj)[tid]);
            const int i0 = tid * 4;
            SP[(i0 >> 5) * 33 + (i0 & 31)]             = p.x;
            SP[((i0 + 1) >> 5) * 33 + ((i0 + 1) & 31)] = p.y;
            SP[((i0 + 2) >> 5) * 33 + ((i0 + 2) & 31)] = p.z;
            SP[((i0 + 3) >> 5) * 33 + ((i0 + 3) & 31)] = p.w;
        }

        // issue K loads early (latency hidden behind barrier + LDS below)
        const int kn = n0 + w;            // this warp's K token
        float4 KL[8];
        {
            const float* kb = k + (size_t)kn * 1024 + fb * 512 + 4 * bm;
            #pragma unroll
            for (int hh = 0; hh < 2; hh++)
                #pragma unroll
                for (int j = 0; j < 4; j++)
                    KL[hh * 4 + j] = __ldg((const float4*)(kb + j * 128 + hh * 64));
        }

        __syncthreads();

        // coefficients from smem: own band row (lane) + partner row (lane^16)
        float4 cO[4], cX[4];
        {
            const float* ro = SP + lane * 33 + 8 * fb;
            const float* rx = SP + (lane ^ 16) * 33 + 8 * fb;
            #pragma unroll
            for (int m = 0; m < 2; m++) {
                cO[m]     = make_float4(ro[4*m], ro[4*m+1], ro[4*m+2], ro[4*m+3]);
                cO[2 + m] = make_float4(ro[16+4*m], ro[16+4*m+1], ro[16+4*m+2], ro[16+4*m+3]);
                cX[m]     = make_float4(rx[4*m], rx[4*m+1], rx[4*m+2], rx[4*m+3]);
                cX[2 + m] = make_float4(rx[16+4*m], rx[16+4*m+1], rx[16+4*m+2], rx[16+4*m+3]);
            }
        }

        // ---- K compute: both halves for token kn ----
        #pragma unroll
        for (int hh = 0; hh < 2; hh++) {
            float aO0 = 0.f, aO1 = 0.f, aX0 = 0.f, aX1 = 0.f;
            #pragma unroll
            for (int j = 0; j < 4; j++) {
                const float4 L = KL[hh * 4 + j];
                const float olo = fb ? L.y : L.x;
                const float ohi = fb ? L.w : L.z;
                const float xlo = fb ? L.x : L.y;
                const float xhi = fb ? L.z : L.w;
                const float4 fol = cO[j >> 1], foh = cO[2 + (j >> 1)];
                const float4 fxl = cX[j >> 1], fxh = cX[2 + (j >> 1)];
                if (j & 1) {
                    aO0 = fmaf(olo, fol.z, fmaf(ohi, foh.z, aO0));
                    aO1 = fmaf(olo, fol.w, fmaf(ohi, foh.w, aO1));
                    aX0 = fmaf(xlo, fxl.z, fmaf(xhi, fxh.z, aX0));
                    aX1 = fmaf(xlo, fxl.w, fmaf(xhi, fxh.w, aX1));
                } else {
                    aO0 = fmaf(olo, fol.x, fmaf(ohi, foh.x, aO0));
                    aO1 = fmaf(olo, fol.y, fmaf(ohi, foh.y, aO1));
                    aX0 = fmaf(xlo, fxl.x, fmaf(xhi, fxh.x, aX0));
                    aX1 = fmaf(xlo, fxl.y, fmaf(xhi, fxh.y, aX1));
                }
            }
            const float a0 = aO0 + __shfl_xor_sync(0xffffffffu, aX0, 16);
            const float a1 = aO1 + __shfl_xor_sync(0xffffffffu, aX1, 16);
            float2* o = (float2*)(out + OUT_K_OFF + (size_t)kn * 128 +
                                  hh * 64 + lane * 2);
            *o = make_float2(a0, a1);
        }

        // ---- Q: 8 tokens, 2-deep software pipeline ----
        const float* qb = q + (size_t)n0 * 4096 + (size_t)fb * 2048 +
                          gr * 128 + hf * 64 + 4 * bm;
        float4 A[4], B[4];
        #pragma unroll
        for (int j = 0; j < 4; j++) A[j] = __ldg((const float4*)(qb + j * 512));
        #pragma unroll
        for (int j = 0; j < 4; j++) B[j] = __ldg((const float4*)(qb + 4096 + j * 512));

        #pragma unroll
        for (int t = 0; t < QK_TPB; t++) {
            float4* Lc = (t & 1) ? B : A;
            float aO0 = 0.f, aO1 = 0.f, aX0 = 0.f, aX1 = 0.f;
            #pragma unroll
            for (int j = 0; j < 4; j++) {
                const float olo = fb ? Lc[j].y : Lc[j].x;
                const float ohi = fb ? Lc[j].w : Lc[j].z;
                const float xlo = fb ? Lc[j].x : Lc[j].y;
                const float xhi = fb ? Lc[j].z : Lc[j].w;
                const float4 fol = cO[j >> 1], foh = cO[2 + (j >> 1)];
                const float4 fxl = cX[j >> 1], fxh = cX[2 + (j >> 1)];
                if (j & 1) {
                    aO0 = fmaf(olo, fol.z, fmaf(ohi, foh.z, aO0));
                    aO1 = fmaf(olo, fol.w, fmaf(ohi, foh.w, aO1));
                    aX0 = fmaf(xlo, fxl.z, fmaf(xhi, fxh.z, aX0));
                    aX1 = fmaf(xlo, fxl.w, fmaf(xhi, fxh.w, aX1));
                } else {
                    aO0 = fmaf(olo, fol.x, fmaf(ohi, foh.x, aO0));
                    aO1 = fmaf(olo, fol.y, fmaf(ohi, foh.y, aO1));
                    aX0 = fmaf(xlo, fxl.x, fmaf(xhi, fxh.x, aX0));
                    aX1 = fmaf(xlo, fxl.y, fmaf(xhi, fxh.y, aX1));
                }
            }
            // prefetch token t+2 into the buffer just consumed
            if (t + 2 < QK_TPB) {
                const float* qn = qb + (size_t)(t + 2) * 4096;
                #pragma unroll
                for (int j = 0; j < 4; j++)
                    Lc[j] = __ldg((const float4*)(qn + j * 512));
            }
            const float a0 = aO0 + __shfl_xor_sync(0xffffffffu, aX0, 16);
            const float a1 = aO1 + __shfl_xor_sync(0xffffffffu, aX1, 16);
            float2* o = (float2*)(out + OUT_Q_OFF + (size_t)(n0 + t) * 512 +
                                  gr * 128 + hf * 64 + lane * 2);
            *o = make_float2(a0, a1);
        }
    } else {
        // ================= W path =================
        float* VS  = smem;            // [W_TPB][1024]
        float* RED = smem + 8192;     // [tok][g][t]

        const int dseg = tid & 7;
        const int t    = (tid >> 3) & 3;
        const int g    = tid >> 5;
        const int h    = g * 4 + t;

        // vt slice in registers
        float4 wt[16];
        {
            const float4* vt4 = (const float4*)vt;
            #pragma unroll
            for (int i = 0; i < 16; i++)
                wt[i] = __ldg(&vt4[h * 128 + dseg + 8 * i]);
        }

        const int n0 = (blockIdx.x - NQK) * W_TPB;

        // stage W_TPB v rows (coalesced)
        {
            const float4* v4 = (const float4*)v + (size_t)n0 * 256;
            float4* vs4 = (float4*)VS;
            #pragma unroll
            for (int j = 0; j < W_TPB; j++)
                vs4[tid + 256 * j] = v4[tid + 256 * j];
        }
        __syncthreads();

        #pragma unroll
        for (int tok = 0; tok < W_TPB; tok++) {
            float4 a = make_float4(0.f, 0.f, 0.f, 0.f);
            float4 b = make_float4(0.f, 0.f, 0.f, 0.f);
            const float* vrow = VS + tok * 1024 + g * 128 + dseg;
            #pragma unroll
            for (int i = 0; i < 16; i += 2) {
                const float f0 = vrow[8 * i];
                const float f1 = vrow[8 * (i + 1)];
                a.x = fmaf(f0, wt[i].x, a.x);     b.x = fmaf(f1, wt[i+1].x, b.x);
                a.y = fmaf(f0, wt[i].y, a.y);     b.y = fmaf(f1, wt[i+1].y, b.y);
                a.z = fmaf(f0, wt[i].z, a.z);     b.z = fmaf(f1, wt[i+1].z, b.z);
                a.w = fmaf(f0, wt[i].w, a.w);     b.w = fmaf(f1, wt[i+1].w, b.w);
            }
            a.x += b.x; a.y += b.y; a.z += b.z; a.w += b.w;
            #pragma unroll
            for (int m = 1; m <= 4; m <<= 1) {
                a.x += __shfl_xor_sync(0xffffffffu, a.x, m);
                a.y += __shfl_xor_sync(0xffffffffu, a.y, m);
                a.z += __shfl_xor_sync(0xffffffffu, a.z, m);
                a.w += __shfl_xor_sync(0xffffffffu, a.w, m);
            }
            if (dseg == 0)
                RED[(tok * 8 + g) * 4 + t] =
                    a.x * a.x + a.y * a.y + a.z * a.z + a.w * a.w;
        }
        __syncthreads();

        if (tid < W_TPB * 4) {
            const int tok = tid >> 2;
            const int tt  = tid & 3;
            float s = 0.f;
            #pragma unroll
            for (int gg = 0; gg < 8; gg++) s += RED[(tok * 8 + gg) * 4 + tt];
            out[OUT_W_OFF + (size_t)(n0 + tok) * 4 + tt] = sqrtf(s);
        }
    }
}

extern "C" void kernel_launch(void* const* d_in, const int* in_sizes, int n_in,
                              void* d_out, int out_size)
{
    const float* q    = (const float*)d_in[0];   // [16384][32][128]
    const float* k    = (const float*)d_in[1];   // [16384][8][128]
    const float* v    = (const float*)d_in[2];   // [16384][8][128]
    const float* proj = (const float*)d_in[3];   // [32][16][2]
    const float* vt   = (const float*)d_in[4];   // [32][128][4]
    float* out = (float*)d_out;

    fused_kernel<<<NQK + NW, 256, SMEM_FLOATS * sizeof(float)>>>(
        q, k, v, proj, vt, out);
}